// round 12
// baseline (speedup 1.0000x reference)
#include <cuda_runtime.h>
#include <cstdint>

// TopK-magnitude masking per row. x: (4096, 8192) fp32, K = 819.
// out[r,c] = x[r,c] if |x[r,c]| >= (K-th largest |x| in row r) else 0.
//
// Structure identical to the 61.5us R5 kernel (one CTA/row, 512 threads,
// row staged in SMEM, plain predicated shared atomics, 4 CTAs/SM), with ONE
// change: the pass-1 histogram is 4-way LANE-replicated (lane&3 picks the
// replica) to cut intra-warp same-address atomic replays ~4x on the
// exponent-clustered Gaussian keys. Radix split 9+11+11 bits so the
// replicated pass-1 hist fits smem (512 bins x 4 = 8 KB).

#define ROWLEN 8192
#define TPB    512
#define KSEL   819u
#define NW     (TPB / 32)   // 16 warps

// Suffix-scan + digit select over h[NB] (B = NB/TPB bins per thread).
// Outputs *sh_digit, *sh_k. Ends with __syncthreads.
template <int NB>
__device__ __forceinline__ void suffix_select(
    const unsigned* __restrict__ h, unsigned k,
    int t, int lane, int wid,
    unsigned* wsum, unsigned* wtail,
    unsigned* sh_digit, unsigned* sh_k)
{
    constexpr int B = NB / TPB;
    const int base = t * B;
    unsigned loc[B];
    unsigned s = 0u;
#pragma unroll
    for (int j = B - 1; j >= 0; j--) { s += h[base + j]; loc[j] = s; }
    unsigned p = s;                        // warp suffix scan of chunk totals
#pragma unroll
    for (int off = 1; off < 32; off <<= 1) {
        unsigned n = __shfl_down_sync(0xFFFFFFFFu, p, off);
        if (lane < 32 - off) p += n;
    }
    if (lane == 0) wsum[wid] = p;
    __syncthreads();
    if (t < NW) {
        unsigned q = wsum[t];
        unsigned r = q;
#pragma unroll
        for (int off = 1; off < NW; off <<= 1) {
            unsigned n = __shfl_down_sync(0x0000FFFFu, r, off);
            if (t < NW - off) r += n;
        }
        wtail[t] = r - q;                  // total of warps AFTER warp t
    }
    __syncthreads();
    unsigned beyond = (p - s) + wtail[wid];
#pragma unroll
    for (int j = 0; j < B; j++) {
        unsigned incl = loc[j] + beyond;                          // count(>=d)
        unsigned cnt  = loc[j] - ((j < B - 1) ? loc[j + 1] : 0u); // hist[d]
        unsigned gt   = incl - cnt;                               // count(>d)
        if (incl >= k && gt < k) { *sh_digit = (unsigned)(base + j); *sh_k = k - gt; }
    }
    __syncthreads();
}

__global__ __launch_bounds__(TPB, 4)
void topk_mask_kernel(const float* __restrict__ x, float* __restrict__ out) {
    __shared__ unsigned row[ROWLEN];     // 32 KB (raw fp32 bits)
    __shared__ unsigned hist[2048];      // 8 KB: pass1 = 4 replicas x 512;
                                         //       pass2/pass3 = 2048 bins
    __shared__ unsigned wsum[NW];
    __shared__ unsigned wtail[NW];
    __shared__ unsigned sh_digit, sh_k;

    const int t    = threadIdx.x;
    const int lane = t & 31;
    const int wid  = t >> 5;
    const size_t row_off = (size_t)blockIdx.x * ROWLEN;
    const uint4* __restrict__ px   = reinterpret_cast<const uint4*>(x + row_off);
    uint4*       __restrict__ po   = reinterpret_cast<uint4*>(out + row_off);
    uint4*                    prow = reinterpret_cast<uint4*>(row);

    // ---- zero pass-1 histogram (2048 words = 1 uint4/thread) ----
    reinterpret_cast<uint4*>(hist)[t] = make_uint4(0u, 0u, 0u, 0u);
    __syncthreads();

    // ---- sweep 1: global load -> smem stage + replicated pass-1 hist ----
    // digit = key >> 22 (9 bits); replica chosen by (lane & 3)
    {
        unsigned* hrep = &hist[(lane & 3) * 512];
#pragma unroll
        for (int i = 0; i < 4; i++) {
            uint4 a = px[t + i * TPB];
            prow[t + i * TPB] = a;
            atomicAdd(&hrep[(a.x & 0x7FFFFFFFu) >> 22], 1u);
            atomicAdd(&hrep[(a.y & 0x7FFFFFFFu) >> 22], 1u);
            atomicAdd(&hrep[(a.z & 0x7FFFFFFFu) >> 22], 1u);
            atomicAdd(&hrep[(a.w & 0x7FFFFFFFu) >> 22], 1u);
        }
    }
    __syncthreads();

    unsigned k = KSEL;
    unsigned d1;

    // ---- select 1: 512 bins (1 bin/thread), summing the 4 replicas ----
    {
        unsigned cnt = hist[t] + hist[512 + t] + hist[1024 + t] + hist[1536 + t];
        unsigned p = cnt;                  // warp suffix scan
#pragma unroll
        for (int off = 1; off < 32; off <<= 1) {
            unsigned n = __shfl_down_sync(0xFFFFFFFFu, p, off);
            if (lane < 32 - off) p += n;
        }
        if (lane == 0) wsum[wid] = p;
        __syncthreads();
        if (t < NW) {
            unsigned q = wsum[t];
            unsigned r = q;
#pragma unroll
            for (int off = 1; off < NW; off <<= 1) {
                unsigned n = __shfl_down_sync(0x0000FFFFu, r, off);
                if (t < NW - off) r += n;
            }
            wtail[t] = r - q;
        }
        __syncthreads();
        unsigned beyond = (p - cnt) + wtail[wid];
        unsigned incl   = cnt + beyond;    // count(>= my bin)
        unsigned gt     = beyond;          // count(>  my bin)
        if (incl >= k && gt < k) { sh_digit = (unsigned)t; sh_k = k - gt; }
        __syncthreads();
        d1 = sh_digit; k = sh_k;
    }

    // ---- sweep 2: pass-2 histogram, bits [11,22), 2048 bins ----
    reinterpret_cast<uint4*>(hist)[t] = make_uint4(0u, 0u, 0u, 0u);
    __syncthreads();
#pragma unroll
    for (int i = 0; i < 4; i++) {
        uint4 a = prow[t + i * TPB];
        const unsigned b[4] = {a.x, a.y, a.z, a.w};
#pragma unroll
        for (int c = 0; c < 4; c++) {
            unsigned kk = b[c] & 0x7FFFFFFFu;
            if ((kk >> 22) == d1)
                atomicAdd(&hist[(kk >> 11) & 0x7FFu], 1u);
        }
    }
    __syncthreads();
    suffix_select<2048>(hist, k, t, lane, wid, wsum, wtail, &sh_digit, &sh_k);
    const unsigned d2 = sh_digit; k = sh_k;
    const unsigned pref20 = (d1 << 11) | d2;   // == key >> 11 for survivors

    // ---- sweep 3: pass-3 histogram, bits [0,11), 2048 bins ----
    reinterpret_cast<uint4*>(hist)[t] = make_uint4(0u, 0u, 0u, 0u);
    __syncthreads();
#pragma unroll
    for (int i = 0; i < 4; i++) {
        uint4 a = prow[t + i * TPB];
        const unsigned b[4] = {a.x, a.y, a.z, a.w};
#pragma unroll
        for (int c = 0; c < 4; c++) {
            unsigned kk = b[c] & 0x7FFFFFFFu;
            if ((kk >> 11) == pref20)
                atomicAdd(&hist[kk & 0x7FFu], 1u);
        }
    }
    __syncthreads();
    suffix_select<2048>(hist, k, t, lane, wid, wsum, wtail, &sh_digit, &sh_k);

    const unsigned T = (pref20 << 11) | sh_digit;   // K-th largest |x| pattern

    // ---- epilogue: mask from smem, coalesced 128-bit store ----
#pragma unroll
    for (int i = 0; i < 4; i++) {
        uint4 a = prow[t + i * TPB];
        const unsigned b[4] = {a.x, a.y, a.z, a.w};
        unsigned o[4];
#pragma unroll
        for (int c = 0; c < 4; c++) {
            unsigned kk = b[c] & 0x7FFFFFFFu;
            o[c] = (kk < T) ? 0u : b[c];
        }
        po[t + i * TPB] = make_uint4(o[0], o[1], o[2], o[3]);
    }
}

extern "C" void kernel_launch(void* const* d_in, const int* in_sizes, int n_in,
                              void* d_out, int out_size) {
    const float* x = (const float*)d_in[0];
    float* out = (float*)d_out;
    const int rows = in_sizes[0] / ROWLEN;   // 4096
    topk_mask_kernel<<<rows, TPB>>>(x, out);
}